// round 2
// baseline (speedup 1.0000x reference)
#include <cuda_runtime.h>
#include <math.h>
#include <stdint.h>

#define SEQ   4096
#define INDIM 64
#define D     1024
#define G     4096      // 4*D
#define NCTA  148
#define RTHR  512

// ---------------- scratch (device globals: allocation-free) ----------------
__device__ float g_x [(size_t)SEQ * D];        // 16 MB  leaky(inp@W1^T+b1)
__device__ float g_xg[(size_t)SEQ * G];        // 64 MB  per-step gate preactivations
__device__ float g_h1[(size_t)SEQ * D];        // 16 MB  layer-1 hidden history
__device__ float g_hbuf[2][D];                 // h double buffer
__device__ unsigned g_flags[NCTA * 32];        // per-CTA epoch flags, 128B apart

// ---------------- init: zero h0 + flag state ----------------
__global__ void init_state_kernel() {
    int tid = threadIdx.x;
    if (tid < D) { g_hbuf[0][tid] = 0.f; g_hbuf[1][tid] = 0.f; }
    for (int i = tid; i < NCTA * 32; i += blockDim.x) g_flags[i] = 0u;
}

// ---------------- SGEMM: C[M,N] = A[M,K] @ B[N,K]^T + bias1 (+bias2), opt leaky ----------------
// BM=BN=128, BK=8, 256 threads, 8x8 per thread.
template<bool RELU>
__global__ __launch_bounds__(256) void sgemm_nt(
    const float* __restrict__ A, const float* __restrict__ B,
    float* __restrict__ C,
    const float* __restrict__ bias1, const float* __restrict__ bias2,
    int M, int N, int K)
{
    __shared__ __align__(16) float As[8][132];
    __shared__ __align__(16) float Bs[8][132];

    const int tid = threadIdx.x;
    const int bm = blockIdx.y, bn = blockIdx.x;
    const int ty = tid >> 4, tx = tid & 15;        // 16x16 thread grid
    const int lrow = tid >> 1;                     // 0..127
    const int lcol = (tid & 1) * 4;                // 0 or 4

    const float* Aptr = A + (size_t)(bm * 128 + lrow) * K + lcol;
    const float* Bptr = B + (size_t)(bn * 128 + lrow) * K + lcol;

    float acc[8][8];
    #pragma unroll
    for (int i = 0; i < 8; i++)
        #pragma unroll
        for (int j = 0; j < 8; j++) acc[i][j] = 0.f;

    for (int k0 = 0; k0 < K; k0 += 8) {
        float4 a = *(const float4*)(Aptr + k0);
        float4 b = *(const float4*)(Bptr + k0);
        __syncthreads();
        As[lcol + 0][lrow] = a.x; As[lcol + 1][lrow] = a.y;
        As[lcol + 2][lrow] = a.z; As[lcol + 3][lrow] = a.w;
        Bs[lcol + 0][lrow] = b.x; Bs[lcol + 1][lrow] = b.y;
        Bs[lcol + 2][lrow] = b.z; Bs[lcol + 3][lrow] = b.w;
        __syncthreads();
        #pragma unroll
        for (int k = 0; k < 8; k++) {
            float4 a0 = *(const float4*)&As[k][ty * 8];
            float4 a1 = *(const float4*)&As[k][ty * 8 + 4];
            float4 b0 = *(const float4*)&Bs[k][tx * 8];
            float4 b1 = *(const float4*)&Bs[k][tx * 8 + 4];
            float av[8] = {a0.x,a0.y,a0.z,a0.w,a1.x,a1.y,a1.z,a1.w};
            float bv[8] = {b0.x,b0.y,b0.z,b0.w,b1.x,b1.y,b1.z,b1.w};
            #pragma unroll
            for (int i = 0; i < 8; i++)
                #pragma unroll
                for (int j = 0; j < 8; j++)
                    acc[i][j] = fmaf(av[i], bv[j], acc[i][j]);
        }
    }

    const int colbase = bn * 128 + tx * 8;
    float bb[8];
    #pragma unroll
    for (int j = 0; j < 8; j++) {
        float v = bias1 ? bias1[colbase + j] : 0.f;
        if (bias2) v += bias2[colbase + j];
        bb[j] = v;
    }
    #pragma unroll
    for (int i = 0; i < 8; i++) {
        int row = bm * 128 + ty * 8 + i;
        float* Crow = C + (size_t)row * N + colbase;
        float o[8];
        #pragma unroll
        for (int j = 0; j < 8; j++) {
            float v = acc[i][j] + bb[j];
            if (RELU) v = v > 0.f ? v : 0.01f * v;
            o[j] = v;
        }
        *(float4*)(Crow)     = make_float4(o[0], o[1], o[2], o[3]);
        *(float4*)(Crow + 4) = make_float4(o[4], o[5], o[6], o[7]);
    }
}

// ---------------- persistent LSTM recurrence ----------------
// 148 CTAs x 512 thr. CTA owns 6-7 units (24-28 gate rows). Whh rows live in
// registers. h_prev staged in smem each step. One distributed-flag grid
// barrier per step: each CTA release-stores its epoch to a padded flag; every
// CTA's warp 0 polls all 148 flags (5 per lane, independent loads).
__device__ __forceinline__ float sigmoidf_(float x) { return 1.f / (1.f + expf(-x)); }

__global__ __launch_bounds__(RTHR, 1) void lstm_recur_kernel(
    const float* __restrict__ Whh,   // [G][D] this layer
    const float* __restrict__ xg,    // [SEQ][G]
    float* __restrict__ h_hist,      // layer-0: g_h1, else unused
    float* __restrict__ out,         // layer-1: final output, else unused
    int store_hist, int store_out)
{
    __shared__ __align__(16) float4 hs4[D / 4];   // h_prev, 1024 floats
    __shared__ float gs[32];
    __shared__ float xgs[32];
    __shared__ int   growtab[32];
    __shared__ float c_s[8];

    const int tid  = threadIdx.x;
    const int lane = tid & 31;
    const int wid  = tid >> 5;
    const int cta  = blockIdx.x;

    const int u_begin = (cta * D) / NCTA;
    const int u_end   = ((cta + 1) * D) / NCTA;
    const int nu      = u_end - u_begin;       // 6 or 7
    const int nrows   = 4 * nu;                // 24 or 28

    if (tid < nrows) {
        int gate = tid / nu, ui = tid % nu;
        growtab[tid] = gate * D + u_begin + ui;  // global gate-row index
    }
    if (tid < nu) c_s[tid] = 0.f;
    __syncthreads();

    // Load this warp's two weight rows into registers (64 regs/thread).
    const int r0 = wid * 2, r1 = r0 + 1;
    const bool act = (r0 < nrows);
    float4 wv0[8], wv1[8];
    if (act) {
        const float4* Wr0 = (const float4*)(Whh + (size_t)growtab[r0] * D);
        const float4* Wr1 = (const float4*)(Whh + (size_t)growtab[r1] * D);
        #pragma unroll
        for (int j = 0; j < 8; j++) {
            wv0[j] = Wr0[j * 32 + lane];
            wv1[j] = Wr1[j * 32 + lane];
        }
    }

    volatile unsigned* my_flag = &g_flags[cta * 32];

    for (int t = 0; t < SEQ; t++) {
        // stage h_prev (L2, bypass L1: cross-SM producer) and xg row slice
        if (tid < 256) {
            hs4[tid] = __ldcg(((const float4*)g_hbuf[t & 1]) + tid);
        } else if (tid - 256 < nrows) {
            int r = tid - 256;
            xgs[r] = __ldg(&xg[(size_t)t * G + growtab[r]]);
        }
        __syncthreads();

        if (act) {
            float acc0 = 0.f, acc1 = 0.f;
            #pragma unroll
            for (int j = 0; j < 8; j++) {
                float4 h4 = hs4[j * 32 + lane];
                acc0 = fmaf(wv0[j].x, h4.x, acc0); acc0 = fmaf(wv0[j].y, h4.y, acc0);
                acc0 = fmaf(wv0[j].z, h4.z, acc0); acc0 = fmaf(wv0[j].w, h4.w, acc0);
                acc1 = fmaf(wv1[j].x, h4.x, acc1); acc1 = fmaf(wv1[j].y, h4.y, acc1);
                acc1 = fmaf(wv1[j].z, h4.z, acc1); acc1 = fmaf(wv1[j].w, h4.w, acc1);
            }
            #pragma unroll
            for (int off = 16; off; off >>= 1) {
                acc0 += __shfl_xor_sync(0xffffffffu, acc0, off);
                acc1 += __shfl_xor_sync(0xffffffffu, acc1, off);
            }
            if (lane == 0) { gs[r0] = acc0; gs[r1] = acc1; }
        }
        __syncthreads();

        if (tid < nu) {
            float gi = gs[0 * nu + tid] + xgs[0 * nu + tid];
            float gf = gs[1 * nu + tid] + xgs[1 * nu + tid];
            float gg = gs[2 * nu + tid] + xgs[2 * nu + tid];
            float go = gs[3 * nu + tid] + xgs[3 * nu + tid];
            float c = c_s[tid];
            c = sigmoidf_(gf) * c + sigmoidf_(gi) * tanhf(gg);
            float h = sigmoidf_(go) * tanhf(c);
            c_s[tid] = c;
            int u = u_begin + tid;
            g_hbuf[(t + 1) & 1][u] = h;
            if (store_hist) h_hist[(size_t)t * D + u] = h;
            if (store_out && t == SEQ - 1) out[u] = h > 0.f ? h : 0.01f * h;
        }
        __syncthreads();   // CTA-wide happens-before for the release below

        if (t + 1 < SEQ) {
            // distributed-flag grid barrier, one per step
            const unsigned want = (unsigned)(t + 1);
            if (wid == 0) {
                if (lane == 0) {
                    __threadfence();        // release this CTA's h stores
                    *my_flag = want;
                }
                // poll all NCTA flags: 5 per lane, independent loads
                for (;;) {
                    unsigned mn = 0xffffffffu;
                    #pragma unroll
                    for (int k = 0; k < 5; k++) {
                        int c = lane + k * 32;
                        if (c < NCTA) {
                            unsigned v = *(volatile unsigned*)&g_flags[c * 32];
                            mn = mn < v ? mn : v;
                        }
                    }
                    if (__all_sync(0xffffffffu, mn >= want)) break;
                }
                __threadfence();            // acquire side
            }
            __syncthreads();
        }
    }
}

// ---------------- launch ----------------
extern "C" void kernel_launch(void* const* d_in, const int* in_sizes, int n_in,
                              void* d_out, int out_size)
{
    const float* inp = (const float*)d_in[0];   // (4096, 64)
    const float* W1  = (const float*)d_in[1];   // (1024, 64)
    const float* b1  = (const float*)d_in[2];   // (1024,)
    const float* Wih = (const float*)d_in[3];   // (2, 4096, 1024)
    const float* Whh = (const float*)d_in[4];   // (2, 4096, 1024)
    const float* bih = (const float*)d_in[5];   // (2, 4096)
    const float* bhh = (const float*)d_in[6];   // (2, 4096)
    float* out = (float*)d_out;                 // (1,1,1024)

    float *gx, *gxg, *gh1;
    cudaGetSymbolAddress((void**)&gx,  g_x);
    cudaGetSymbolAddress((void**)&gxg, g_xg);
    cudaGetSymbolAddress((void**)&gh1, g_h1);

    // Phase A: x = leaky_relu(inp @ W1^T + b1)       [4096 x 1024, K=64]
    sgemm_nt<true><<<dim3(D / 128, SEQ / 128), 256>>>(
        inp, W1, gx, b1, nullptr, SEQ, D, INDIM);

    // Phase B: xg1 = x @ Wih1^T + (bih1 + bhh1)      [4096 x 4096, K=1024]
    sgemm_nt<false><<<dim3(G / 128, SEQ / 128), 256>>>(
        gx, Wih, gxg, bih, bhh, SEQ, G, D);

    // Layer-1 recurrence (writes g_h1)
    init_state_kernel<<<1, 1024>>>();
    lstm_recur_kernel<<<NCTA, RTHR>>>(Whh, gxg, gh1, out, 1, 0);

    // Phase C: xg2 = h1 @ Wih2^T + (bih2 + bhh2)
    sgemm_nt<false><<<dim3(G / 128, SEQ / 128), 256>>>(
        gh1, Wih + (size_t)G * D, gxg, bih + G, bhh + G, SEQ, G, D);

    // Layer-2 recurrence (writes final leaky_relu(h_T) to out)
    init_state_kernel<<<1, 1024>>>();
    lstm_recur_kernel<<<NCTA, RTHR>>>(Whh + (size_t)G * D, gxg, gh1, out, 0, 1);
}

// round 3
// speedup vs baseline: 1.0275x; 1.0275x over previous
#include <cuda_runtime.h>
#include <math.h>
#include <stdint.h>

#define SEQ   4096
#define INDIM 64
#define D     1024
#define G     4096      // 4*D
#define NCTA  148
#define RTHR  512

typedef unsigned long long u64;

// ---------------- scratch (device globals: allocation-free) ----------------
__device__ float g_x [(size_t)SEQ * D];        // 16 MB
__device__ float g_xg[(size_t)SEQ * G];        // 64 MB
__device__ float g_h1[(size_t)SEQ * D];        // 16 MB
__device__ float g_hbuf[2][D];
__device__ unsigned g_flags[NCTA * 32];        // per-CTA epoch flags, 128B apart

// ---------------- packed f32x2 helpers (Blackwell) ----------------
#define FMA2(d,a,b,c)  asm("fma.rn.f32x2 %0,%1,%2,%3;" : "=l"(d) : "l"(a), "l"(b), "l"(c))
#define PACK2(d,x)     asm("mov.b64 %0,{%1,%1};"       : "=l"(d) : "f"(x))
#define UNPACK2(lo,hi,v) asm("mov.b64 {%0,%1},%2;"     : "=f"(lo), "=f"(hi) : "l"(v))

__device__ __forceinline__ float sigmoid_fast(float x) {
    return 1.f / (1.f + __expf(-x));            // MUFU.EX2 + MUFU.RCP path
}
__device__ __forceinline__ float tanh_fast(float x) {
    return 2.f / (1.f + __expf(-2.f * x)) - 1.f;
}

// ---------------- init: zero h0 + flag state ----------------
__global__ void init_state_kernel() {
    int tid = threadIdx.x;
    if (tid < D) { g_hbuf[0][tid] = 0.f; g_hbuf[1][tid] = 0.f; }
    for (int i = tid; i < NCTA * 32; i += blockDim.x) g_flags[i] = 0u;
}

// ---------------- SGEMM: C = A@B^T + bias1(+bias2), opt leaky; f32x2 inner ----------------
template<bool RELU>
__global__ __launch_bounds__(256) void sgemm_nt(
    const float* __restrict__ A, const float* __restrict__ B,
    float* __restrict__ C,
    const float* __restrict__ bias1, const float* __restrict__ bias2,
    int M, int N, int K)
{
    __shared__ __align__(16) float As[8][132];
    __shared__ __align__(16) float Bs[8][132];

    const int tid = threadIdx.x;
    const int bm = blockIdx.y, bn = blockIdx.x;
    const int ty = tid >> 4, tx = tid & 15;
    const int lrow = tid >> 1;
    const int lcol = (tid & 1) * 4;

    const float* Aptr = A + (size_t)(bm * 128 + lrow) * K + lcol;
    const float* Bptr = B + (size_t)(bn * 128 + lrow) * K + lcol;

    u64 acc2[8][4];
    #pragma unroll
    for (int i = 0; i < 8; i++)
        #pragma unroll
        for (int j = 0; j < 4; j++) acc2[i][j] = 0ull;

    for (int k0 = 0; k0 < K; k0 += 8) {
        float4 a = *(const float4*)(Aptr + k0);
        float4 b = *(const float4*)(Bptr + k0);
        __syncthreads();
        As[lcol + 0][lrow] = a.x; As[lcol + 1][lrow] = a.y;
        As[lcol + 2][lrow] = a.z; As[lcol + 3][lrow] = a.w;
        Bs[lcol + 0][lrow] = b.x; Bs[lcol + 1][lrow] = b.y;
        Bs[lcol + 2][lrow] = b.z; Bs[lcol + 3][lrow] = b.w;
        __syncthreads();
        #pragma unroll
        for (int k = 0; k < 8; k++) {
            float4 a0 = *(const float4*)&As[k][ty * 8];
            float4 a1 = *(const float4*)&As[k][ty * 8 + 4];
            const ulonglong2* bp = (const ulonglong2*)&Bs[k][tx * 8];
            ulonglong2 q0 = bp[0], q1 = bp[1];
            u64 bv[4] = {q0.x, q0.y, q1.x, q1.y};
            float av[8] = {a0.x,a0.y,a0.z,a0.w,a1.x,a1.y,a1.z,a1.w};
            u64 aa[8];
            #pragma unroll
            for (int i = 0; i < 8; i++) PACK2(aa[i], av[i]);
            #pragma unroll
            for (int i = 0; i < 8; i++)
                #pragma unroll
                for (int j = 0; j < 4; j++)
                    FMA2(acc2[i][j], aa[i], bv[j], acc2[i][j]);
        }
    }

    const int colbase = bn * 128 + tx * 8;
    float bb[8];
    #pragma unroll
    for (int j = 0; j < 8; j++) {
        float v = bias1 ? bias1[colbase + j] : 0.f;
        if (bias2) v += bias2[colbase + j];
        bb[j] = v;
    }
    #pragma unroll
    for (int i = 0; i < 8; i++) {
        int row = bm * 128 + ty * 8 + i;
        float* Crow = C + (size_t)row * N + colbase;
        float o[8];
        #pragma unroll
        for (int j = 0; j < 4; j++) UNPACK2(o[2*j], o[2*j+1], acc2[i][j]);
        #pragma unroll
        for (int j = 0; j < 8; j++) {
            float v = o[j] + bb[j];
            if (RELU) v = v > 0.f ? v : 0.01f * v;
            o[j] = v;
        }
        *(float4*)(Crow)     = make_float4(o[0], o[1], o[2], o[3]);
        *(float4*)(Crow + 4) = make_float4(o[4], o[5], o[6], o[7]);
    }
}

// ---------------- persistent LSTM recurrence ----------------
// 148 CTAs x 512 thr. CTA owns 6-7 units (24-28 gate rows). Whh in registers
// (warp w: rows 2w,2w+1 as f32x2 pairs). xg(t+1) prefetched into registers a
// full step ahead. One distributed-flag grid barrier per step with
// relaxed-poll / release-store semantics.
__global__ __launch_bounds__(RTHR, 1) void lstm_recur_kernel(
    const float* __restrict__ Whh,   // [G][D] this layer
    const float* __restrict__ xg,    // [SEQ][G]
    float* __restrict__ h_hist,
    float* __restrict__ out,
    int store_hist, int store_out)
{
    __shared__ __align__(16) u64 hs2[D / 2];      // h_prev as f32x2 pairs
    __shared__ float gs[32];
    __shared__ float xgs[32];
    __shared__ float c_s[8];

    const int tid  = threadIdx.x;
    const int lane = tid & 31;
    const int wid  = tid >> 5;
    const int cta  = blockIdx.x;

    const int u_begin = (cta * D) / NCTA;
    const int u_end   = ((cta + 1) * D) / NCTA;
    const int nu      = u_end - u_begin;       // 6 or 7
    const int nrows   = 4 * nu;                // 24 or 28

    if (tid < nu) c_s[tid] = 0.f;

    // xg loader threads: tid in [256, 256+nrows)
    const bool ldr = (tid >= 256) && (tid - 256 < nrows);
    int my_grow = 0; float xr = 0.f;
    if (ldr) {
        int r = tid - 256;
        int gate = r / nu, ui = r - gate * nu;
        my_grow = gate * D + u_begin + ui;
        xr = __ldg(&xg[my_grow]);              // prefetch t=0
    }

    // Compute warps: rows r0=2w, r1=2w+1 (local), weights in registers as f32x2.
    const int r0 = wid * 2, r1 = r0 + 1;
    const bool act = (r0 < nrows);
    ulonglong2 wr0[8], wr1[8];
    if (act) {
        int g0 = r0 / nu, g1 = r1 / nu;
        int grow0 = g0 * D + u_begin + (r0 - g0 * nu);
        int grow1 = g1 * D + u_begin + (r1 - g1 * nu);
        const ulonglong2* W0 = (const ulonglong2*)(Whh + (size_t)grow0 * D);
        const ulonglong2* W1 = (const ulonglong2*)(Whh + (size_t)grow1 * D);
        #pragma unroll
        for (int j = 0; j < 8; j++) {
            wr0[j] = W0[j * 32 + lane];
            wr1[j] = W1[j * 32 + lane];
        }
    }
    __syncthreads();

    unsigned* my_flag = &g_flags[cta * 32];

    for (int t = 0; t < SEQ; t++) {
        // stage h_prev (bypass L1; producers on other SMs) + xg from prefetch regs
        if (tid < 256) {
            float4 v = __ldcg(((const float4*)g_hbuf[t & 1]) + tid);
            ((float4*)hs2)[tid] = v;
        } else if (ldr) {
            xgs[tid - 256] = xr;
            if (t + 1 < SEQ) xr = __ldg(&xg[(size_t)(t + 1) * G + my_grow]);
        }
        __syncthreads();

        if (act) {
            u64 a0 = 0ull, a1 = 0ull, b0 = 0ull, b1 = 0ull;
            #pragma unroll
            for (int j = 0; j < 8; j++) {
                ulonglong2 hv = ((const ulonglong2*)hs2)[j * 32 + lane];
                FMA2(a0, wr0[j].x, hv.x, a0);
                FMA2(a1, wr0[j].y, hv.y, a1);
                FMA2(b0, wr1[j].x, hv.x, b0);
                FMA2(b1, wr1[j].y, hv.y, b1);
            }
            float a0l, a0h, a1l, a1h, b0l, b0h, b1l, b1h;
            UNPACK2(a0l, a0h, a0); UNPACK2(a1l, a1h, a1);
            UNPACK2(b0l, b0h, b0); UNPACK2(b1l, b1h, b1);
            float acc0 = (a0l + a0h) + (a1l + a1h);
            float acc1 = (b0l + b0h) + (b1l + b1h);
            #pragma unroll
            for (int off = 16; off; off >>= 1) {
                acc0 += __shfl_xor_sync(0xffffffffu, acc0, off);
                acc1 += __shfl_xor_sync(0xffffffffu, acc1, off);
            }
            if (lane == 0) { gs[r0] = acc0; gs[r1] = acc1; }
        }
        __syncthreads();

        if (tid < nu) {
            float gi = gs[0 * nu + tid] + xgs[0 * nu + tid];
            float gf = gs[1 * nu + tid] + xgs[1 * nu + tid];
            float gg = gs[2 * nu + tid] + xgs[2 * nu + tid];
            float go = gs[3 * nu + tid] + xgs[3 * nu + tid];
            float c = c_s[tid];
            c = sigmoid_fast(gf) * c + sigmoid_fast(gi) * tanh_fast(gg);
            float h = sigmoid_fast(go) * tanh_fast(c);
            c_s[tid] = c;
            int u = u_begin + tid;
            g_hbuf[(t + 1) & 1][u] = h;
            if (store_hist) h_hist[(size_t)t * D + u] = h;
            if (store_out && t == SEQ - 1) out[u] = h > 0.f ? h : 0.01f * h;
        }
        __syncthreads();   // CTA-wide happens-before for the release below

        if (t + 1 < SEQ) {
            const unsigned want = (unsigned)(t + 1);
            if (wid == 0) {
                if (lane == 0) {
                    // release-store: publishes this CTA's h stores (HB via bar.sync)
                    asm volatile("st.release.gpu.u32 [%0], %1;" :: "l"(my_flag), "r"(want) : "memory");
                }
                // poll all NCTA flags with relaxed loads (5 per lane, MLP)
                for (;;) {
                    unsigned mn = 0xffffffffu;
                    #pragma unroll
                    for (int k = 0; k < 5; k++) {
                        int c = lane + k * 32;
                        if (c < NCTA) {
                            unsigned v;
                            asm volatile("ld.relaxed.gpu.u32 %0, [%1];"
                                         : "=r"(v) : "l"(&g_flags[c * 32]) : "memory");
                            mn = mn < v ? mn : v;
                        }
                    }
                    if (__all_sync(0xffffffffu, mn >= want)) break;
                }
                asm volatile("fence.acq_rel.gpu;" ::: "memory");   // acquire side
            }
            __syncthreads();
        }
    }
}

// ---------------- launch ----------------
extern "C" void kernel_launch(void* const* d_in, const int* in_sizes, int n_in,
                              void* d_out, int out_size)
{
    const float* inp = (const float*)d_in[0];   // (4096, 64)
    const float* W1  = (const float*)d_in[1];   // (1024, 64)
    const float* b1  = (const float*)d_in[2];   // (1024,)
    const float* Wih = (const float*)d_in[3];   // (2, 4096, 1024)
    const float* Whh = (const float*)d_in[4];   // (2, 4096, 1024)
    const float* bih = (const float*)d_in[5];   // (2, 4096)
    const float* bhh = (const float*)d_in[6];   // (2, 4096)
    float* out = (float*)d_out;                 // (1,1,1024)

    float *gx, *gxg, *gh1;
    cudaGetSymbolAddress((void**)&gx,  g_x);
    cudaGetSymbolAddress((void**)&gxg, g_xg);
    cudaGetSymbolAddress((void**)&gh1, g_h1);

    // Phase A: x = leaky_relu(inp @ W1^T + b1)
    sgemm_nt<true><<<dim3(D / 128, SEQ / 128), 256>>>(
        inp, W1, gx, b1, nullptr, SEQ, D, INDIM);

    // Phase B: xg1 = x @ Wih1^T + (bih1 + bhh1)
    sgemm_nt<false><<<dim3(G / 128, SEQ / 128), 256>>>(
        gx, Wih, gxg, bih, bhh, SEQ, G, D);

    // Layer-1 recurrence (writes g_h1)
    init_state_kernel<<<1, 1024>>>();
    lstm_recur_kernel<<<NCTA, RTHR>>>(Whh, gxg, gh1, out, 1, 0);

    // Phase C: xg2 = h1 @ Wih2^T + (bih2 + bhh2)
    sgemm_nt<false><<<dim3(G / 128, SEQ / 128), 256>>>(
        gh1, Wih + (size_t)G * D, gxg, bih + G, bhh + G, SEQ, G, D);

    // Layer-2 recurrence (writes final leaky_relu(h_T) to out)
    init_state_kernel<<<1, 1024>>>();
    lstm_recur_kernel<<<NCTA, RTHR>>>(Whh + (size_t)G * D, gxg, gh1, out, 0, 1);
}

// round 4
// speedup vs baseline: 1.3202x; 1.2849x over previous
#include <cuda_runtime.h>
#include <math.h>
#include <stdint.h>

#define SEQ   4096
#define INDIM 64
#define D     1024
#define G     4096      // 4*D
#define NCTA  148
#define RTHR  512
#define NCHUNK (NCTA * 3)   // 444 LL packets (3 per CTA, some partial/inactive)

typedef unsigned long long u64;

// ---------------- scratch (device globals: allocation-free) ----------------
__device__ float g_x [(size_t)SEQ * D];        // 16 MB
__device__ float g_xg[(size_t)SEQ * G];        // 64 MB
__device__ float g_h1[(size_t)SEQ * D];        // 16 MB
// LL packets: [slot][cta][chunk] = {h0,h1,h2, epoch_bits}
__device__ float4 g_ll[2][NCTA][3];

// ---------------- packed f32x2 helpers (Blackwell) ----------------
#define FMA2(d,a,b,c)  asm("fma.rn.f32x2 %0,%1,%2,%3;" : "=l"(d) : "l"(a), "l"(b), "l"(c))
#define PACK2(d,x)     asm("mov.b64 %0,{%1,%1};"       : "=l"(d) : "f"(x))
#define UNPACK2(lo,hi,v) asm("mov.b64 {%0,%1},%2;"     : "=f"(lo), "=f"(hi) : "l"(v))

__device__ __forceinline__ float sigmoid_fast(float x) {
    return 1.f / (1.f + __expf(-x));
}
__device__ __forceinline__ float tanh_fast(float x) {
    return 2.f / (1.f + __expf(-2.f * x)) - 1.f;
}

// 16B volatile (L2-coherent, single-sector-atomic) load/store — NCCL LL style.
__device__ __forceinline__ float4 ll_load(const float4* p) {
    float4 v;
    asm volatile("ld.volatile.global.v4.f32 {%0,%1,%2,%3}, [%4];"
                 : "=f"(v.x), "=f"(v.y), "=f"(v.z), "=f"(v.w) : "l"(p) : "memory");
    return v;
}
__device__ __forceinline__ void ll_store(float4* p, float4 v) {
    asm volatile("st.volatile.global.v4.f32 [%0], {%1,%2,%3,%4};"
                 :: "l"(p), "f"(v.x), "f"(v.y), "f"(v.z), "f"(v.w) : "memory");
}

// ---------------- init: zero LL packets (epoch=0, h=0) ----------------
__global__ void init_state_kernel() {
    int tid = threadIdx.x;
    float4 z = make_float4(0.f, 0.f, 0.f, 0.f);
    for (int i = tid; i < 2 * NCTA * 3; i += blockDim.x)
        ((float4*)g_ll)[i] = z;
}

// ---------------- SGEMM: C = A@B^T + bias1(+bias2), opt leaky; f32x2 inner ----------------
template<bool RELU>
__global__ __launch_bounds__(256) void sgemm_nt(
    const float* __restrict__ A, const float* __restrict__ B,
    float* __restrict__ C,
    const float* __restrict__ bias1, const float* __restrict__ bias2,
    int M, int N, int K)
{
    __shared__ __align__(16) float As[8][132];
    __shared__ __align__(16) float Bs[8][132];

    const int tid = threadIdx.x;
    const int bm = blockIdx.y, bn = blockIdx.x;
    const int ty = tid >> 4, tx = tid & 15;
    const int lrow = tid >> 1;
    const int lcol = (tid & 1) * 4;

    const float* Aptr = A + (size_t)(bm * 128 + lrow) * K + lcol;
    const float* Bptr = B + (size_t)(bn * 128 + lrow) * K + lcol;

    u64 acc2[8][4];
    #pragma unroll
    for (int i = 0; i < 8; i++)
        #pragma unroll
        for (int j = 0; j < 4; j++) acc2[i][j] = 0ull;

    for (int k0 = 0; k0 < K; k0 += 8) {
        float4 a = *(const float4*)(Aptr + k0);
        float4 b = *(const float4*)(Bptr + k0);
        __syncthreads();
        As[lcol + 0][lrow] = a.x; As[lcol + 1][lrow] = a.y;
        As[lcol + 2][lrow] = a.z; As[lcol + 3][lrow] = a.w;
        Bs[lcol + 0][lrow] = b.x; Bs[lcol + 1][lrow] = b.y;
        Bs[lcol + 2][lrow] = b.z; Bs[lcol + 3][lrow] = b.w;
        __syncthreads();
        #pragma unroll
        for (int k = 0; k < 8; k++) {
            float4 a0 = *(const float4*)&As[k][ty * 8];
            float4 a1 = *(const float4*)&As[k][ty * 8 + 4];
            const ulonglong2* bp = (const ulonglong2*)&Bs[k][tx * 8];
            ulonglong2 q0 = bp[0], q1 = bp[1];
            u64 bv[4] = {q0.x, q0.y, q1.x, q1.y};
            float av[8] = {a0.x,a0.y,a0.z,a0.w,a1.x,a1.y,a1.z,a1.w};
            u64 aa[8];
            #pragma unroll
            for (int i = 0; i < 8; i++) PACK2(aa[i], av[i]);
            #pragma unroll
            for (int i = 0; i < 8; i++)
                #pragma unroll
                for (int j = 0; j < 4; j++)
                    FMA2(acc2[i][j], aa[i], bv[j], acc2[i][j]);
        }
    }

    const int colbase = bn * 128 + tx * 8;
    float bb[8];
    #pragma unroll
    for (int j = 0; j < 8; j++) {
        float v = bias1 ? bias1[colbase + j] : 0.f;
        if (bias2) v += bias2[colbase + j];
        bb[j] = v;
    }
    #pragma unroll
    for (int i = 0; i < 8; i++) {
        int row = bm * 128 + ty * 8 + i;
        float* Crow = C + (size_t)row * N + colbase;
        float o[8];
        #pragma unroll
        for (int j = 0; j < 4; j++) UNPACK2(o[2*j], o[2*j+1], acc2[i][j]);
        #pragma unroll
        for (int j = 0; j < 8; j++) {
            float v = o[j] + bb[j];
            if (RELU) v = v > 0.f ? v : 0.01f * v;
            o[j] = v;
        }
        *(float4*)(Crow)     = make_float4(o[0], o[1], o[2], o[3]);
        *(float4*)(Crow + 4) = make_float4(o[4], o[5], o[6], o[7]);
    }
}

// ---------------- persistent LSTM recurrence (LL protocol) ----------------
// 148 CTAs x 512 thr, 1 CTA/SM.
//   warps 0-13 : poll all 444 LL packets (1/lane) -> scatter h into smem; then
//                register-resident matvec (2 gate rows/warp) + shfl reduce.
//   warp 14    : xg(t+1) register prefetch.
//   warp 15    : gate nonlinearities (28 lanes parallel), c-state in registers,
//                h gather via shfl, publish LL packets {h0,h1,h2,epoch=t+1}.
// Epochs: iteration t consumes epoch t from slot t&1, publishes epoch t+1 to
// slot (t+1)&1. Safe: overwriting slot t-1 requires having consumed ALL of t,
// which implies every CTA is done consuming t-1.
__global__ __launch_bounds__(RTHR, 1) void lstm_recur_kernel(
    const float* __restrict__ Whh,   // [G][D] this layer
    const float* __restrict__ xg,    // [SEQ][G]
    float* __restrict__ h_hist,
    float* __restrict__ out,
    int store_hist, int store_out)
{
    __shared__ __align__(16) float hs[D];   // assembled h(t)
    __shared__ float gs[32];
    __shared__ float xgs[32];

    const int tid  = threadIdx.x;
    const int lane = tid & 31;
    const int wid  = tid >> 5;
    const int cta  = blockIdx.x;

    const int u_begin = (cta * D) / NCTA;
    const int u_end   = ((cta + 1) * D) / NCTA;
    const int nu      = u_end - u_begin;       // 6 or 7
    const int nrows   = 4 * nu;                // 24 or 28

    // ---- poller mapping (tid < 444): chunk tid = (cta c, sub k) ----
    const bool pact = (tid < NCHUNK);
    int p_ub = 0, p_n = 0;
    const float4* p_src0 = nullptr;   // slot 0 address
    const float4* p_src1 = nullptr;   // slot 1 address
    if (pact) {
        int c = tid / 3, k = tid - c * 3;
        int cb = (c * D) / NCTA, ce = ((c + 1) * D) / NCTA;
        p_ub = cb + 3 * k;
        p_n  = ce - p_ub; p_n = p_n > 3 ? 3 : p_n;   // may be <=0 -> inactive
        p_src0 = &g_ll[0][c][k];
        p_src1 = &g_ll[1][c][k];
    }
    const bool p_on = pact && (p_n > 0);

    // ---- xg prefetch threads (warp 14) ----
    const bool ldr = (tid >= 448) && (tid - 448 < nrows);
    int my_grow = 0; float xr = 0.f;
    if (ldr) {
        int r = tid - 448;
        int gate = r / nu, ui = r - gate * nu;
        my_grow = gate * D + u_begin + ui;
        xr = __ldg(&xg[my_grow]);              // prefetch t=0
    }

    // ---- matvec warps 0-13: rows r0=2w, r1=2w+1, weights in registers ----
    const int r0 = wid * 2, r1 = r0 + 1;
    const bool act = (wid < 14) && (r0 < nrows);
    ulonglong2 wr0[8], wr1[8];
    if (act) {
        int gg0 = r0 / nu, gg1 = r1 / nu;
        int grow0 = gg0 * D + u_begin + (r0 - gg0 * nu);
        int grow1 = gg1 * D + u_begin + (r1 - gg1 * nu);
        const ulonglong2* W0 = (const ulonglong2*)(Whh + (size_t)grow0 * D);
        const ulonglong2* W1 = (const ulonglong2*)(Whh + (size_t)grow1 * D);
        #pragma unroll
        for (int j = 0; j < 8; j++) {
            wr0[j] = W0[j * 32 + lane];
            wr1[j] = W1[j * 32 + lane];
        }
    }

    // ---- warp 15: gate lane roles (constants across loop) ----
    const bool gw = (wid == 15);
    int g_of = 0, u_of = 0;
    bool g_on = false, u_on = false;
    float c_reg = 0.f;
    float4* pub0 = nullptr; float4* pub1 = nullptr;
    bool pub_on = false;
    if (gw) {
        g_on = lane < nrows;
        g_of = g_on ? lane / nu : 0;
        u_of = g_on ? lane - g_of * nu : 0;
        u_on = lane < nu;
        pub_on = (lane < 3) && (3 * lane < nu);
        if (lane < 3) { pub0 = &g_ll[0][cta][lane]; pub1 = &g_ll[1][cta][lane]; }
    }
    __syncthreads();

    for (int t = 0; t < SEQ; t++) {
        // ---- phase 1: ingest h(t) via LL packets / stage xg(t) ----
        if (p_on) {
            const float4* src = (t & 1) ? p_src1 : p_src0;
            float4 v;
            do { v = ll_load(src); } while (__float_as_uint(v.w) != (unsigned)t);
            hs[p_ub] = v.x;
            if (p_n > 1) hs[p_ub + 1] = v.y;
            if (p_n > 2) hs[p_ub + 2] = v.z;
        } else if (ldr) {
            xgs[tid - 448] = xr;
            if (t + 1 < SEQ) xr = __ldg(&xg[(size_t)(t + 1) * G + my_grow]);
        }
        __syncthreads();

        // ---- phase 2: matvec + warp reduce ----
        if (act) {
            u64 a0 = 0ull, a1 = 0ull, b0 = 0ull, b1 = 0ull;
            #pragma unroll
            for (int j = 0; j < 8; j++) {
                ulonglong2 hv = ((const ulonglong2*)hs)[j * 32 + lane];
                FMA2(a0, wr0[j].x, hv.x, a0);
                FMA2(a1, wr0[j].y, hv.y, a1);
                FMA2(b0, wr1[j].x, hv.x, b0);
                FMA2(b1, wr1[j].y, hv.y, b1);
            }
            float a0l, a0h, a1l, a1h, b0l, b0h, b1l, b1h;
            UNPACK2(a0l, a0h, a0); UNPACK2(a1l, a1h, a1);
            UNPACK2(b0l, b0h, b0); UNPACK2(b1l, b1h, b1);
            float acc0 = (a0l + a0h) + (a1l + a1h);
            float acc1 = (b0l + b0h) + (b1l + b1h);
            #pragma unroll
            for (int off = 16; off; off >>= 1) {
                acc0 += __shfl_xor_sync(0xffffffffu, acc0, off);
                acc1 += __shfl_xor_sync(0xffffffffu, acc1, off);
            }
            if (lane == 0) { gs[r0] = acc0; gs[r1] = acc1; }
        }
        __syncthreads();

        // ---- phase 3: gates + publish (warp 15 only) ----
        if (gw) {
            float nl = 0.f;
            if (g_on) {
                float val = gs[lane] + xgs[lane];
                nl = (g_of == 2) ? tanh_fast(val) : sigmoid_fast(val);
            }
            // gather the 4 gate values for unit u_of (lanes u, nu+u, 2nu+u, 3nu+u)
            float gi = __shfl_sync(0xffffffffu, nl, lane);            // self (i-gate region lanes)
            gi       = __shfl_sync(0xffffffffu, nl, 0 * nu + lane);
            float gf = __shfl_sync(0xffffffffu, nl, 1 * nu + lane);
            float gg = __shfl_sync(0xffffffffu, nl, 2 * nu + lane);
            float go = __shfl_sync(0xffffffffu, nl, 3 * nu + lane);
            float h = 0.f;
            if (u_on) {
                c_reg = gf * c_reg + gi * gg;
                float tc = tanh_fast(c_reg);
                h = go * tc;
                if (store_hist) h_hist[(size_t)t * D + u_begin + lane] = h;
                if (store_out && t == SEQ - 1) {
                    float o = h > 0.f ? h : 0.01f * h;
                    out[u_begin + lane] = o;
                }
            }
            // pack chunks: lane k grabs h of units 3k,3k+1,3k+2
            float h0 = __shfl_sync(0xffffffffu, h, 3 * lane + 0);
            float h1 = __shfl_sync(0xffffffffu, h, 3 * lane + 1);
            float h2 = __shfl_sync(0xffffffffu, h, 3 * lane + 2);
            if (pub_on && t + 1 < SEQ) {
                float4 pkt = make_float4(h0, h1, h2, __uint_as_float((unsigned)(t + 1)));
                ll_store(((t + 1) & 1) ? pub1 : pub0, pkt);
            }
        }
        __syncthreads();   // protect hs/xgs/gs for next iteration
    }
}

// ---------------- launch ----------------
extern "C" void kernel_launch(void* const* d_in, const int* in_sizes, int n_in,
                              void* d_out, int out_size)
{
    const float* inp = (const float*)d_in[0];   // (4096, 64)
    const float* W1  = (const float*)d_in[1];   // (1024, 64)
    const float* b1  = (const float*)d_in[2];   // (1024,)
    const float* Wih = (const float*)d_in[3];   // (2, 4096, 1024)
    const float* Whh = (const float*)d_in[4];   // (2, 4096, 1024)
    const float* bih = (const float*)d_in[5];   // (2, 4096)
    const float* bhh = (const float*)d_in[6];   // (2, 4096)
    float* out = (float*)d_out;                 // (1,1,1024)

    float *gx, *gxg, *gh1;
    cudaGetSymbolAddress((void**)&gx,  g_x);
    cudaGetSymbolAddress((void**)&gxg, g_xg);
    cudaGetSymbolAddress((void**)&gh1, g_h1);

    // Phase A: x = leaky_relu(inp @ W1^T + b1)
    sgemm_nt<true><<<dim3(D / 128, SEQ / 128), 256>>>(
        inp, W1, gx, b1, nullptr, SEQ, D, INDIM);

    // Phase B: xg1 = x @ Wih1^T + (bih1 + bhh1)
    sgemm_nt<false><<<dim3(G / 128, SEQ / 128), 256>>>(
        gx, Wih, gxg, bih, bhh, SEQ, G, D);

    // Layer-1 recurrence (writes g_h1)
    init_state_kernel<<<1, 1024>>>();
    lstm_recur_kernel<<<NCTA, RTHR>>>(Whh, gxg, gh1, out, 1, 0);

    // Phase C: xg2 = h1 @ Wih2^T + (bih2 + bhh2)
    sgemm_nt<false><<<dim3(G / 128, SEQ / 128), 256>>>(
        gh1, Wih + (size_t)G * D, gxg, bih + G, bhh + G, SEQ, G, D);

    // Layer-2 recurrence (writes final leaky_relu(h_T) to out)
    init_state_kernel<<<1, 1024>>>();
    lstm_recur_kernel<<<NCTA, RTHR>>>(Whh + (size_t)G * D, gxg, gh1, out, 0, 1);
}